// round 4
// baseline (speedup 1.0000x reference)
#include <cuda_runtime.h>

// Problem constants
constexpr int Bb  = 2;
constexpr int Cc  = 256;
constexpr int Hh  = 56;
constexpr int Ww  = 96;
constexpr int HWv = Hh * Ww;          // 5376
constexpr int Nn  = Bb * HWv;         // 10752

// Pyramid dims
constexpr int H1 = 28, W1 = 48;
constexpr int H2 = 14, W2 = 24;
constexpr int H3 = 7,  W3 = 12;

// Scratch: transposed (channels-last) feature maps + pooled pyramid
__device__ float g_f1t[(size_t)Bb * HWv * Cc];
__device__ float g_f20[(size_t)Bb * HWv * Cc];
__device__ float g_f21[(size_t)Bb * H1 * W1 * Cc];
__device__ float g_f22[(size_t)Bb * H2 * W2 * Cc];
__device__ float g_f23[(size_t)Bb * H3 * W3 * Cc];

// ---------------------------------------------------------------------------
// Transpose [B, C, HW] -> [B, HW, C]  (32x32 shared tile)
// which == 0 -> g_f1t, which == 1 -> g_f20
// ---------------------------------------------------------------------------
__global__ void transpose_k(const float* __restrict__ in, int which) {
    __shared__ float tile[32][33];
    float* out = which ? g_f20 : g_f1t;
    int b   = blockIdx.z;
    int hw0 = blockIdx.x * 32;
    int c0  = blockIdx.y * 32;
    const float* ib = in  + (size_t)b * Cc * HWv;
    float*       ob = out + (size_t)b * HWv * Cc;
    int tx = threadIdx.x, ty = threadIdx.y;   // 32 x 8
#pragma unroll
    for (int r = 0; r < 32; r += 8)
        tile[ty + r][tx] = ib[(size_t)(c0 + ty + r) * HWv + hw0 + tx];
    __syncthreads();
#pragma unroll
    for (int r = 0; r < 32; r += 8)
        ob[(size_t)(hw0 + ty + r) * Cc + c0 + tx] = tile[tx][ty + r];
}

// ---------------------------------------------------------------------------
// 2x2 avg pool on channels-last layout. level selects in/out buffers.
// grid: (Ho*Wo, B), block: 256 threads (= channels)
// ---------------------------------------------------------------------------
__global__ void pool_k(int level) {
    const float* in; float* out; int Wi, Wo, Ho;
    if (level == 1)      { in = g_f20; out = g_f21; Wi = 96; Wo = 48; Ho = 28; }
    else if (level == 2) { in = g_f21; out = g_f22; Wi = 48; Wo = 24; Ho = 14; }
    else                 { in = g_f22; out = g_f23; Wi = 24; Wo = 12; Ho = 7;  }
    int HiWi = (2 * Ho) * Wi;
    int HoWo = Ho * Wo;
    int b = blockIdx.y, p = blockIdx.x, c = threadIdx.x;
    int y = p / Wo, x = p - y * Wo;
    const float* ib = in + (size_t)b * HiWi * Cc;
    size_t i00 = ((size_t)(2 * y) * Wi + 2 * x) * Cc + c;
    size_t rs  = (size_t)Wi * Cc;
    float v = ib[i00] + ib[i00 + Cc] + ib[i00 + rs] + ib[i00 + rs + Cc];
    out[((size_t)b * HoWo + p) * Cc + c] = 0.25f * v;
}

// ---------------------------------------------------------------------------
// Correlation lookup. One block = one query pixel.
// 256 threads = 8 warps; each warp = four 8-lane dot groups.
// Per level: 100 integer-position dots (10x10 window), then 81 bilinear
// combines with shared (wx, wy). Zero padding via validity mask (branchless,
// so 8-lane shfl reductions never diverge).
// ---------------------------------------------------------------------------
__global__ __launch_bounds__(256) void lookup_k(const float* __restrict__ coords,
                                                float* __restrict__ out) {
    int n   = blockIdx.x;
    int b   = n / HWv;
    int rem = n - b * HWv;
    int lane = threadIdx.x & 31;
    int w    = threadIdx.x >> 5;   // warp 0..7
    int sub  = lane >> 3;          // dot slot within warp 0..3
    int li   = lane & 7;           // lane within dot group 0..7

    // Query vector chunk: lane li owns channels [li*32, li*32+32)
    const float4* f1v = (const float4*)(g_f1t + (size_t)n * Cc);
    float4 a[8];
#pragma unroll
    for (int k = 0; k < 8; k++) a[k] = f1v[li * 8 + k];

    float cx = coords[(size_t)b * 2 * HWv + rem];
    float cy = coords[(size_t)b * 2 * HWv + HWv + rem];

    __shared__ float sD[100];

    const float* lp[4] = { g_f20, g_f21, g_f22, g_f23 };
    const int Hs[4] = { Hh, H1, H2, H3 };
    const int Ws[4] = { Ww, W1, W2, W3 };

#pragma unroll
    for (int l = 0; l < 4; l++) {
        float inv = 1.0f / (float)(1 << l);
        float px = cx * inv, py = cy * inv;
        float fx = floorf(px), fy = floorf(py);
        int x0 = (int)fx, y0 = (int)fy;
        float wx = px - fx, wy = py - fy;
        int Hl = Hs[l], Wl = Ws[l];
        const float* base = lp[l] + (size_t)b * Hl * Wl * Cc;

        // 32 dot-slots per iteration (8 warps x 4 subs); 4 iterations cover 100
#pragma unroll
        for (int it = 0; it < 4; it++) {
            int d  = it * 32 + (w << 2) + sub;
            int dc = d < 100 ? d : 99;
            int xi = dc / 10, yj = dc - xi * 10;
            int gx = x0 - 4 + xi;
            int gy = y0 - 4 + yj;
            bool valid = (gx >= 0) & (gx < Wl) & (gy >= 0) & (gy < Hl);
            int cgx = min(max(gx, 0), Wl - 1);
            int cgy = min(max(gy, 0), Hl - 1);
            const float4* col = (const float4*)(base + ((size_t)cgy * Wl + cgx) * Cc);
            float s = 0.f;
#pragma unroll
            for (int k = 0; k < 8; k++) {
                float4 bb = col[li * 8 + k];
                s += a[k].x * bb.x + a[k].y * bb.y + a[k].z * bb.z + a[k].w * bb.w;
            }
            s = valid ? s : 0.f;
            // reduce within 8-lane group (all lanes converged)
            s += __shfl_xor_sync(0xffffffffu, s, 1);
            s += __shfl_xor_sync(0xffffffffu, s, 2);
            s += __shfl_xor_sync(0xffffffffu, s, 4);
            if (li == 0 && d < 100) sD[d] = s * 0.0625f;  // 1/sqrt(256)
        }
        __syncthreads();

        int t = threadIdx.x;
        if (t < 81) {
            // sample index s = ix*9 + iy (xo varies along axis 0 per reference)
            int ix = t / 9, iy = t - ix * 9;
            float d00 = sD[ix * 10 + iy];
            float d10 = sD[ix * 10 + 10 + iy];
            float d01 = sD[ix * 10 + iy + 1];
            float d11 = sD[ix * 10 + 11 + iy];
            float v = (1.f - wy) * ((1.f - wx) * d00 + wx * d10)
                    +        wy  * ((1.f - wx) * d01 + wx * d11);
            out[((size_t)b * 324 + l * 81 + t) * HWv + rem] = v;
        }
        __syncthreads();
    }
}

// ---------------------------------------------------------------------------
// Convex upsample. One block = one coarse pixel, 64 threads = 8x8 subpixels.
// ---------------------------------------------------------------------------
__global__ __launch_bounds__(64) void upsample_k(const float* __restrict__ flow,
                                                 const float* __restrict__ mask,
                                                 float* __restrict__ out) {
    int n   = blockIdx.x;
    int b   = n / HWv;
    int rem = n - b * HWv;
    int y = rem / Ww, x = rem - y * Ww;
    __shared__ float pf[18];   // [ch][k] 3x3 patch of 8*flow, zero-padded
    int t = threadIdx.x;
    if (t < 18) {
        int ch = t / 9, k = t - ch * 9;
        int i = k / 3, j = k - i * 3;
        int yy = y + i - 1, xx = x + j - 1;
        float v = 0.f;
        if (yy >= 0 && yy < Hh && xx >= 0 && xx < Ww)
            v = 8.f * flow[((size_t)b * 2 + ch) * HWv + yy * Ww + xx];
        pf[t] = v;
    }
    __syncthreads();

    float mv[9];
    float mmax = -1e30f;
    const float* mb = mask + (size_t)b * 576 * HWv + rem;
#pragma unroll
    for (int k = 0; k < 9; k++) {
        mv[k] = mb[(size_t)(k * 64 + t) * HWv];
        mmax = fmaxf(mmax, mv[k]);
    }
    float se = 0.f;
#pragma unroll
    for (int k = 0; k < 9; k++) { mv[k] = __expf(mv[k] - mmax); se += mv[k]; }
    float r = 1.f / se;
    float s0 = 0.f, s1 = 0.f;
#pragma unroll
    for (int k = 0; k < 9; k++) { s0 += mv[k] * pf[k]; s1 += mv[k] * pf[9 + k]; }
    s0 *= r; s1 *= r;

    int p8 = t >> 3, q8 = t & 7;
    int oy = y * 8 + p8, ox = x * 8 + q8;
    size_t OFFU = (size_t)Bb * 324 * HWv;
    size_t plane = (size_t)(Hh * 8) * (Ww * 8);
    float* ob = out + OFFU + (size_t)b * 2 * plane;
    ob[(size_t)oy * (Ww * 8) + ox]         = s0;
    ob[plane + (size_t)oy * (Ww * 8) + ox] = s1;
}

// ---------------------------------------------------------------------------
extern "C" void kernel_launch(void* const* d_in, const int* in_sizes, int n_in,
                              void* d_out, int out_size) {
    const float* fmap1  = (const float*)d_in[0];
    const float* fmap2  = (const float*)d_in[1];
    const float* coords = (const float*)d_in[2];
    const float* flow   = (const float*)d_in[3];
    const float* mask   = (const float*)d_in[4];
    float* out = (float*)d_out;

    dim3 tb(32, 8);
    dim3 tg(HWv / 32, Cc / 32, Bb);
    transpose_k<<<tg, tb>>>(fmap1, 0);
    transpose_k<<<tg, tb>>>(fmap2, 1);
    pool_k<<<dim3(H1 * W1, Bb), Cc>>>(1);
    pool_k<<<dim3(H2 * W2, Bb), Cc>>>(2);
    pool_k<<<dim3(H3 * W3, Bb), Cc>>>(3);
    lookup_k<<<Nn, 256>>>(coords, out);
    upsample_k<<<Nn, 64>>>(flow, mask, out);
}

// round 5
// speedup vs baseline: 2.8769x; 2.8769x over previous
#include <cuda_runtime.h>
#include <cuda_fp16.h>

// Problem constants
constexpr int Bb  = 2;
constexpr int Cc  = 256;
constexpr int Hh  = 56;
constexpr int Ww  = 96;
constexpr int HWv = Hh * Ww;          // 5376
constexpr int Nn  = Bb * HWv;         // 10752

// Pyramid dims
constexpr int H1 = 28, W1 = 48;
constexpr int H2 = 14, W2 = 24;
constexpr int H3 = 7,  W3 = 12;

// Scratch: fp32 transposed query map; fp16 channels-last fmap2 pyramid
__device__ float  g_f1t[(size_t)Bb * HWv * Cc];
__device__ __half g_f20[(size_t)Bb * HWv * Cc];
__device__ __half g_f21[(size_t)Bb * H1 * W1 * Cc];
__device__ __half g_f22[(size_t)Bb * H2 * W2 * Cc];
__device__ __half g_f23[(size_t)Bb * H3 * W3 * Cc];

// ---------------------------------------------------------------------------
// Transpose [B, C, HW] -> [B, HW, C] fp32 (query map)
// ---------------------------------------------------------------------------
__global__ void transpose_f_k(const float* __restrict__ in) {
    __shared__ float tile[32][33];
    int b   = blockIdx.z;
    int hw0 = blockIdx.x * 32;
    int c0  = blockIdx.y * 32;
    const float* ib = in     + (size_t)b * Cc * HWv;
    float*       ob = g_f1t  + (size_t)b * HWv * Cc;
    int tx = threadIdx.x, ty = threadIdx.y;   // 32 x 8
#pragma unroll
    for (int r = 0; r < 32; r += 8)
        tile[ty + r][tx] = ib[(size_t)(c0 + ty + r) * HWv + hw0 + tx];
    __syncthreads();
#pragma unroll
    for (int r = 0; r < 32; r += 8)
        ob[(size_t)(hw0 + ty + r) * Cc + c0 + tx] = tile[tx][ty + r];
}

// ---------------------------------------------------------------------------
// Transpose [B, C, HW] -> [B, HW, C] with fp32 -> fp16 convert (fmap2 base)
// ---------------------------------------------------------------------------
__global__ void transpose_h_k(const float* __restrict__ in) {
    __shared__ float tile[32][33];
    int b   = blockIdx.z;
    int hw0 = blockIdx.x * 32;
    int c0  = blockIdx.y * 32;
    const float* ib = in    + (size_t)b * Cc * HWv;
    __half*      ob = g_f20 + (size_t)b * HWv * Cc;
    int tx = threadIdx.x, ty = threadIdx.y;   // 32 x 8
#pragma unroll
    for (int r = 0; r < 32; r += 8)
        tile[ty + r][tx] = ib[(size_t)(c0 + ty + r) * HWv + hw0 + tx];
    __syncthreads();
#pragma unroll
    for (int r = 0; r < 32; r += 8)
        ob[(size_t)(hw0 + ty + r) * Cc + c0 + tx] = __float2half_rn(tile[tx][ty + r]);
}

// ---------------------------------------------------------------------------
// 2x2 avg pool on channels-last fp16 layout. 128 threads = 128 half2 lanes.
// ---------------------------------------------------------------------------
__global__ void pool_k(int level) {
    const __half* in; __half* out; int Wi, Wo, Ho;
    if (level == 1)      { in = g_f20; out = g_f21; Wi = 96; Wo = 48; Ho = 28; }
    else if (level == 2) { in = g_f21; out = g_f22; Wi = 48; Wo = 24; Ho = 14; }
    else                 { in = g_f22; out = g_f23; Wi = 24; Wo = 12; Ho = 7;  }
    int HiWi = (2 * Ho) * Wi;
    int HoWo = Ho * Wo;
    int b = blockIdx.y, p = blockIdx.x, c = threadIdx.x;   // c in [0,128) half2 units
    int y = p / Wo, x = p - y * Wo;
    const __half2* ib = (const __half2*)(in + (size_t)b * HiWi * Cc);
    size_t i00 = ((size_t)(2 * y) * Wi + 2 * x) * (Cc / 2) + c;
    size_t rs  = (size_t)Wi * (Cc / 2);
    float2 v0 = __half22float2(ib[i00]);
    float2 v1 = __half22float2(ib[i00 + Cc / 2]);
    float2 v2 = __half22float2(ib[i00 + rs]);
    float2 v3 = __half22float2(ib[i00 + rs + Cc / 2]);
    float2 s;
    s.x = 0.25f * (v0.x + v1.x + v2.x + v3.x);
    s.y = 0.25f * (v0.y + v1.y + v2.y + v3.y);
    ((__half2*)(out + ((size_t)b * HoWo + p) * Cc))[c] = __floats2half2_rn(s.x, s.y);
}

// ---------------------------------------------------------------------------
// Correlation lookup. One block = one query pixel.
// 256 threads = 8 warps; each warp = four 8-lane dot groups.
// Pyramid columns are fp16 (512B each); query stays fp32 in registers;
// products/accumulation in fp32.
// ---------------------------------------------------------------------------
__global__ __launch_bounds__(256) void lookup_k(const float* __restrict__ coords,
                                                float* __restrict__ out) {
    int n   = blockIdx.x;
    int b   = n / HWv;
    int rem = n - b * HWv;
    int lane = threadIdx.x & 31;
    int w    = threadIdx.x >> 5;   // warp 0..7
    int sub  = lane >> 3;          // dot slot within warp 0..3
    int li   = lane & 7;           // lane within dot group 0..7

    // Query vector chunk: lane li owns channels [li*32, li*32+32), fp32
    const float4* f1v = (const float4*)(g_f1t + (size_t)n * Cc) + li * 8;
    float a[32];
#pragma unroll
    for (int k = 0; k < 8; k++) {
        float4 q = f1v[k];
        a[4 * k]     = q.x;
        a[4 * k + 1] = q.y;
        a[4 * k + 2] = q.z;
        a[4 * k + 3] = q.w;
    }

    float cx = coords[(size_t)b * 2 * HWv + rem];
    float cy = coords[(size_t)b * 2 * HWv + HWv + rem];

    __shared__ float sD[100];

    const __half* lp[4] = { g_f20, g_f21, g_f22, g_f23 };
    const int Hs[4] = { Hh, H1, H2, H3 };
    const int Ws[4] = { Ww, W1, W2, W3 };

#pragma unroll
    for (int l = 0; l < 4; l++) {
        float inv = 1.0f / (float)(1 << l);
        float px = cx * inv, py = cy * inv;
        float fx = floorf(px), fy = floorf(py);
        int x0 = (int)fx, y0 = (int)fy;
        float wx = px - fx, wy = py - fy;
        int Hl = Hs[l], Wl = Ws[l];
        const __half* base = lp[l] + (size_t)b * Hl * Wl * Cc;

        // 32 dot-slots per iteration (8 warps x 4 subs); 4 iterations cover 100
#pragma unroll
        for (int it = 0; it < 4; it++) {
            int d  = it * 32 + (w << 2) + sub;
            int dc = d < 100 ? d : 99;
            int xi = dc / 10, yj = dc - xi * 10;
            int gx = x0 - 4 + xi;
            int gy = y0 - 4 + yj;
            bool valid = (gx >= 0) & (gx < Wl) & (gy >= 0) & (gy < Hl);
            int cgx = min(max(gx, 0), Wl - 1);
            int cgy = min(max(gy, 0), Hl - 1);
            // fp16 column: 512B; lane li reads 4 x 16B (= 32 channels)
            const uint4* col =
                (const uint4*)(base + ((size_t)cgy * Wl + cgx) * Cc) + li * 4;
            float s0 = 0.f, s1 = 0.f;
#pragma unroll
            for (int k = 0; k < 4; k++) {
                uint4 r = col[k];
                const __half2* h = reinterpret_cast<const __half2*>(&r);
#pragma unroll
                for (int j = 0; j < 4; j++) {
                    float2 f = __half22float2(h[j]);
                    s0 = fmaf(a[k * 8 + 2 * j],     f.x, s0);
                    s1 = fmaf(a[k * 8 + 2 * j + 1], f.y, s1);
                }
            }
            float s = s0 + s1;
            s = valid ? s : 0.f;
            // reduce within 8-lane group (all lanes converged)
            s += __shfl_xor_sync(0xffffffffu, s, 1);
            s += __shfl_xor_sync(0xffffffffu, s, 2);
            s += __shfl_xor_sync(0xffffffffu, s, 4);
            if (li == 0 && d < 100) sD[d] = s * 0.0625f;  // 1/sqrt(256)
        }
        __syncthreads();

        int t = threadIdx.x;
        if (t < 81) {
            // sample index s = ix*9 + iy (xo varies along axis 0 per reference)
            int ix = t / 9, iy = t - ix * 9;
            float d00 = sD[ix * 10 + iy];
            float d10 = sD[ix * 10 + 10 + iy];
            float d01 = sD[ix * 10 + iy + 1];
            float d11 = sD[ix * 10 + 11 + iy];
            float v = (1.f - wy) * ((1.f - wx) * d00 + wx * d10)
                    +        wy  * ((1.f - wx) * d01 + wx * d11);
            out[((size_t)b * 324 + l * 81 + t) * HWv + rem] = v;
        }
        __syncthreads();
    }
}

// ---------------------------------------------------------------------------
// Convex upsample. One block = one coarse pixel, 64 threads = 8x8 subpixels.
// ---------------------------------------------------------------------------
__global__ __launch_bounds__(64) void upsample_k(const float* __restrict__ flow,
                                                 const float* __restrict__ mask,
                                                 float* __restrict__ out) {
    int n   = blockIdx.x;
    int b   = n / HWv;
    int rem = n - b * HWv;
    int y = rem / Ww, x = rem - y * Ww;
    __shared__ float pf[18];   // [ch][k] 3x3 patch of 8*flow, zero-padded
    int t = threadIdx.x;
    if (t < 18) {
        int ch = t / 9, k = t - ch * 9;
        int i = k / 3, j = k - i * 3;
        int yy = y + i - 1, xx = x + j - 1;
        float v = 0.f;
        if (yy >= 0 && yy < Hh && xx >= 0 && xx < Ww)
            v = 8.f * flow[((size_t)b * 2 + ch) * HWv + yy * Ww + xx];
        pf[t] = v;
    }
    __syncthreads();

    float mv[9];
    float mmax = -1e30f;
    const float* mb = mask + (size_t)b * 576 * HWv + rem;
#pragma unroll
    for (int k = 0; k < 9; k++) {
        mv[k] = mb[(size_t)(k * 64 + t) * HWv];
        mmax = fmaxf(mmax, mv[k]);
    }
    float se = 0.f;
#pragma unroll
    for (int k = 0; k < 9; k++) { mv[k] = __expf(mv[k] - mmax); se += mv[k]; }
    float r = 1.f / se;
    float s0 = 0.f, s1 = 0.f;
#pragma unroll
    for (int k = 0; k < 9; k++) { s0 += mv[k] * pf[k]; s1 += mv[k] * pf[9 + k]; }
    s0 *= r; s1 *= r;

    int p8 = t >> 3, q8 = t & 7;
    int oy = y * 8 + p8, ox = x * 8 + q8;
    size_t OFFU = (size_t)Bb * 324 * HWv;
    size_t plane = (size_t)(Hh * 8) * (Ww * 8);
    float* ob = out + OFFU + (size_t)b * 2 * plane;
    ob[(size_t)oy * (Ww * 8) + ox]         = s0;
    ob[plane + (size_t)oy * (Ww * 8) + ox] = s1;
}

// ---------------------------------------------------------------------------
extern "C" void kernel_launch(void* const* d_in, const int* in_sizes, int n_in,
                              void* d_out, int out_size) {
    const float* fmap1  = (const float*)d_in[0];
    const float* fmap2  = (const float*)d_in[1];
    const float* coords = (const float*)d_in[2];
    const float* flow   = (const float*)d_in[3];
    const float* mask   = (const float*)d_in[4];
    float* out = (float*)d_out;

    dim3 tb(32, 8);
    dim3 tg(HWv / 32, Cc / 32, Bb);
    transpose_f_k<<<tg, tb>>>(fmap1);
    transpose_h_k<<<tg, tb>>>(fmap2);
    pool_k<<<dim3(H1 * W1, Bb), 128>>>(1);
    pool_k<<<dim3(H2 * W2, Bb), 128>>>(2);
    pool_k<<<dim3(H3 * W3, Bb), 128>>>(3);
    lookup_k<<<Nn, 256>>>(coords, out);
    upsample_k<<<Nn, 64>>>(flow, mask, out);
}

// round 6
// speedup vs baseline: 4.0153x; 1.3957x over previous
#include <cuda_runtime.h>
#include <cuda_fp16.h>

// Problem constants
constexpr int Bb  = 2;
constexpr int Cc  = 256;
constexpr int Hh  = 56;
constexpr int Ww  = 96;
constexpr int HWv = Hh * Ww;          // 5376
constexpr int Nn  = Bb * HWv;         // 10752

// Pyramid dims
constexpr int H1 = 28, W1 = 48;
constexpr int H2 = 14, W2 = 24;
constexpr int H3 = 7,  W3 = 12;

// Scratch: fp32 transposed query map; fp16 channels-last fmap2 pyramid;
// compact per-pixel corr output staged for a coalescing transpose
__device__ float  g_f1t[(size_t)Bb * HWv * Cc];
__device__ __half g_f20[(size_t)Bb * HWv * Cc];
__device__ __half g_f21[(size_t)Bb * H1 * W1 * Cc];
__device__ __half g_f22[(size_t)Bb * H2 * W2 * Cc];
__device__ __half g_f23[(size_t)Bb * H3 * W3 * Cc];
__device__ float  g_corr[(size_t)Nn * 324];

// ---------------------------------------------------------------------------
// Transpose [B, C, HW] -> [B, HW, C] fp32 (query map)
// ---------------------------------------------------------------------------
__global__ void transpose_f_k(const float* __restrict__ in) {
    __shared__ float tile[32][33];
    int b   = blockIdx.z;
    int hw0 = blockIdx.x * 32;
    int c0  = blockIdx.y * 32;
    const float* ib = in     + (size_t)b * Cc * HWv;
    float*       ob = g_f1t  + (size_t)b * HWv * Cc;
    int tx = threadIdx.x, ty = threadIdx.y;   // 32 x 8
#pragma unroll
    for (int r = 0; r < 32; r += 8)
        tile[ty + r][tx] = ib[(size_t)(c0 + ty + r) * HWv + hw0 + tx];
    __syncthreads();
#pragma unroll
    for (int r = 0; r < 32; r += 8)
        ob[(size_t)(hw0 + ty + r) * Cc + c0 + tx] = tile[tx][ty + r];
}

// ---------------------------------------------------------------------------
// Transpose [B, C, HW] -> [B, HW, C] with fp32 -> fp16 convert (fmap2 base)
// ---------------------------------------------------------------------------
__global__ void transpose_h_k(const float* __restrict__ in) {
    __shared__ float tile[32][33];
    int b   = blockIdx.z;
    int hw0 = blockIdx.x * 32;
    int c0  = blockIdx.y * 32;
    const float* ib = in    + (size_t)b * Cc * HWv;
    __half*      ob = g_f20 + (size_t)b * HWv * Cc;
    int tx = threadIdx.x, ty = threadIdx.y;   // 32 x 8
#pragma unroll
    for (int r = 0; r < 32; r += 8)
        tile[ty + r][tx] = ib[(size_t)(c0 + ty + r) * HWv + hw0 + tx];
    __syncthreads();
#pragma unroll
    for (int r = 0; r < 32; r += 8)
        ob[(size_t)(hw0 + ty + r) * Cc + c0 + tx] = __float2half_rn(tile[tx][ty + r]);
}

// ---------------------------------------------------------------------------
// 2x2 avg pool on channels-last fp16 layout. 128 threads = 128 half2 lanes.
// ---------------------------------------------------------------------------
__global__ void pool_k(int level) {
    const __half* in; __half* out; int Wi, Wo, Ho;
    if (level == 1)      { in = g_f20; out = g_f21; Wi = 96; Wo = 48; Ho = 28; }
    else if (level == 2) { in = g_f21; out = g_f22; Wi = 48; Wo = 24; Ho = 14; }
    else                 { in = g_f22; out = g_f23; Wi = 24; Wo = 12; Ho = 7;  }
    int HiWi = (2 * Ho) * Wi;
    int HoWo = Ho * Wo;
    int b = blockIdx.y, p = blockIdx.x, c = threadIdx.x;   // c in [0,128) half2 units
    int y = p / Wo, x = p - y * Wo;
    const __half2* ib = (const __half2*)(in + (size_t)b * HiWi * Cc);
    size_t i00 = ((size_t)(2 * y) * Wi + 2 * x) * (Cc / 2) + c;
    size_t rs  = (size_t)Wi * (Cc / 2);
    float2 v0 = __half22float2(ib[i00]);
    float2 v1 = __half22float2(ib[i00 + Cc / 2]);
    float2 v2 = __half22float2(ib[i00 + rs]);
    float2 v3 = __half22float2(ib[i00 + rs + Cc / 2]);
    float2 s;
    s.x = 0.25f * (v0.x + v1.x + v2.x + v3.x);
    s.y = 0.25f * (v0.y + v1.y + v2.y + v3.y);
    ((__half2*)(out + ((size_t)b * HoWo + p) * Cc))[c] = __floats2half2_rn(s.x, s.y);
}

// ---------------------------------------------------------------------------
// Correlation lookup. One block = 2x2 tile of query pixels (L1 reuse of
// overlapping windows). 256 threads = 8 warps; warps w and w+4 serve pixel
// w&3. Each warp = four 8-lane dot groups -> 8 dot slots per pixel per
// iteration; 13 iterations cover the 100-position window per level.
// Results written to compact [n][324] scratch (coalesced).
// ---------------------------------------------------------------------------
__global__ __launch_bounds__(256) void lookup_k(const float* __restrict__ coords) {
    int b   = blockIdx.z;
    int x0b = blockIdx.x * 2;
    int y0b = blockIdx.y * 2;
    int t    = threadIdx.x;
    int w    = t >> 5;            // warp 0..7
    int lane = t & 31;
    int pp   = w & 3;             // pixel within 2x2 tile
    int hw4  = w >> 2;            // 0 or 1 (which warp-pair half)
    int sub  = lane >> 3;         // dot slot within warp 0..3
    int li   = lane & 7;          // lane within dot group 0..7

    int pyy = y0b + (pp >> 1);
    int pxx = x0b + (pp & 1);
    int rem = pyy * Ww + pxx;
    int n   = b * HWv + rem;

    // Query vector chunk: lane li owns channels [li*32, li*32+32), fp32
    const float4* f1v = (const float4*)(g_f1t + (size_t)n * Cc) + li * 8;
    float a[32];
#pragma unroll
    for (int k = 0; k < 8; k++) {
        float4 q = f1v[k];
        a[4 * k]     = q.x;
        a[4 * k + 1] = q.y;
        a[4 * k + 2] = q.z;
        a[4 * k + 3] = q.w;
    }

    float cx = coords[(size_t)b * 2 * HWv + rem];
    float cy = coords[(size_t)b * 2 * HWv + HWv + rem];

    __shared__ float sD[4][100];
    __shared__ float sW[4][2];
    __shared__ int   sR[4];
    if (w < 4 && lane == 0) sR[w] = rem;

    const __half* lp[4] = { g_f20, g_f21, g_f22, g_f23 };
    const int Hs[4] = { Hh, H1, H2, H3 };
    const int Ws[4] = { Ww, W1, W2, W3 };

#pragma unroll
    for (int l = 0; l < 4; l++) {
        float inv = 1.0f / (float)(1 << l);
        float px = cx * inv, py = cy * inv;
        float fx = floorf(px), fy = floorf(py);
        int x0 = (int)fx, y0 = (int)fy;
        float wx = px - fx, wy = py - fy;
        if (w < 4 && lane == 0) { sW[w][0] = wx; sW[w][1] = wy; }
        int Hl = Hs[l], Wl = Ws[l];
        const __half* base = lp[l] + (size_t)b * Hl * Wl * Cc;

#pragma unroll 1
        for (int it = 0; it < 13; it++) {
            int d  = it * 8 + hw4 * 4 + sub;
            int dc = d < 100 ? d : 99;
            int xi = dc / 10, yj = dc - xi * 10;
            int gx = x0 - 4 + xi;
            int gy = y0 - 4 + yj;
            bool valid = (gx >= 0) & (gx < Wl) & (gy >= 0) & (gy < Hl) & (d < 100);
            int cgx = min(max(gx, 0), Wl - 1);
            int cgy = min(max(gy, 0), Hl - 1);
            // fp16 column: 512B; lane li reads 4 x 16B (= 32 channels)
            const uint4* col =
                (const uint4*)(base + ((size_t)cgy * Wl + cgx) * Cc) + li * 4;
            float s0 = 0.f, s1 = 0.f;
#pragma unroll
            for (int k = 0; k < 4; k++) {
                uint4 r = col[k];
                const __half2* h = reinterpret_cast<const __half2*>(&r);
#pragma unroll
                for (int j = 0; j < 4; j++) {
                    float2 f = __half22float2(h[j]);
                    s0 = fmaf(a[k * 8 + 2 * j],     f.x, s0);
                    s1 = fmaf(a[k * 8 + 2 * j + 1], f.y, s1);
                }
            }
            float s = s0 + s1;
            s = valid ? s : 0.f;
            // reduce within 8-lane group (all lanes converged)
            s += __shfl_xor_sync(0xffffffffu, s, 1);
            s += __shfl_xor_sync(0xffffffffu, s, 2);
            s += __shfl_xor_sync(0xffffffffu, s, 4);
            if (li == 0 && d < 100) sD[pp][d] = s * 0.0625f;  // 1/sqrt(256)
        }
        __syncthreads();

        for (int u = t; u < 324; u += 256) {
            int P  = u / 81;
            int s_ = u - P * 81;
            int ix = s_ / 9, iy = s_ - ix * 9;
            float wxp = sW[P][0], wyp = sW[P][1];
            float d00 = sD[P][ix * 10 + iy];
            float d10 = sD[P][ix * 10 + 10 + iy];
            float d01 = sD[P][ix * 10 + iy + 1];
            float d11 = sD[P][ix * 10 + 11 + iy];
            float v = (1.f - wyp) * ((1.f - wxp) * d00 + wxp * d10)
                    +        wyp  * ((1.f - wxp) * d01 + wxp * d11);
            g_corr[((size_t)b * HWv + sR[P]) * 324 + l * 81 + s_] = v;
        }
        __syncthreads();
    }
}

// ---------------------------------------------------------------------------
// Transpose compact corr [B*HW][324] -> out [B][324][HW] (coalesced both sides)
// ---------------------------------------------------------------------------
__global__ void corr_t_k(float* __restrict__ out) {
    __shared__ float tile[32][33];
    int b  = blockIdx.z;
    int r0 = blockIdx.x * 32;   // rem tile
    int c0 = blockIdx.y * 32;   // channel tile (0..323)
    int tx = threadIdx.x, ty = threadIdx.y;   // 32 x 8
#pragma unroll
    for (int r = 0; r < 32; r += 8) {
        int c = c0 + tx;
        float v = 0.f;
        if (c < 324)
            v = g_corr[((size_t)b * HWv + r0 + ty + r) * 324 + c];
        tile[ty + r][tx] = v;
    }
    __syncthreads();
#pragma unroll
    for (int r = 0; r < 32; r += 8) {
        int c = c0 + ty + r;
        if (c < 324)
            out[((size_t)b * 324 + c) * HWv + r0 + tx] = tile[tx][ty + r];
    }
}

// ---------------------------------------------------------------------------
// Convex upsample, coalesced. One block = 32 consecutive coarse pixels in a
// row (96 % 32 == 0, no row wrap). 256 threads: warp = subpixel row p8,
// lane = pixel. All mask reads are lane-coalesced; each thread emits 8
// contiguous floats per channel (two float4 stores).
// ---------------------------------------------------------------------------
__global__ __launch_bounds__(256) void upsample_k(const float* __restrict__ flow,
                                                  const float* __restrict__ mask,
                                                  float* __restrict__ out) {
    int rem0 = blockIdx.x * 32;
    int b  = rem0 / HWv;
    int r  = rem0 - b * HWv;
    int y  = r / Ww;
    int x0 = r - y * Ww;

    __shared__ float pfc[2][3][34];   // 3x3 neighborhoods of 8*flow for 32 pixels
    int t = threadIdx.x;
    if (t < 204) {
        int ch = t / 102, q = t - ch * 102;
        int dy = q / 34,  dx = q - dy * 34;
        int gy = y - 1 + dy, gx = x0 - 1 + dx;
        float v = 0.f;
        if (gy >= 0 && gy < Hh && gx >= 0 && gx < Ww)
            v = 8.f * flow[((size_t)b * 2 + ch) * HWv + gy * Ww + gx];
        pfc[ch][dy][dx] = v;
    }
    __syncthreads();

    int w = t >> 5;        // p8 (subpixel row)
    int lane = t & 31;     // pixel within the 32-pixel strip
    int rem = r + lane;
    const float* mb = mask + (size_t)b * 576 * HWv + rem;

    float o0[8], o1[8];
#pragma unroll
    for (int q8 = 0; q8 < 8; q8++) {
        float mv[9];
        float mmax = -1e30f;
#pragma unroll
        for (int k = 0; k < 9; k++) {
            mv[k] = mb[(size_t)(k * 64 + w * 8 + q8) * HWv];
            mmax = fmaxf(mmax, mv[k]);
        }
        float se = 0.f;
#pragma unroll
        for (int k = 0; k < 9; k++) { mv[k] = __expf(mv[k] - mmax); se += mv[k]; }
        float rr = 1.f / se;
        float s0 = 0.f, s1 = 0.f;
#pragma unroll
        for (int k = 0; k < 9; k++) {
            int i = k / 3, j = k - i * 3;
            s0 += mv[k] * pfc[0][i][lane + j];
            s1 += mv[k] * pfc[1][i][lane + j];
        }
        o0[q8] = s0 * rr;
        o1[q8] = s1 * rr;
    }

    size_t OFFU  = (size_t)Bb * 324 * HWv;
    size_t plane = (size_t)(Hh * 8) * (Ww * 8);
    int oy = y * 8 + w;
    float* p0 = out + OFFU + (size_t)b * 2 * plane
              + (size_t)oy * (Ww * 8) + (size_t)(x0 + lane) * 8;
    ((float4*)p0)[0] = make_float4(o0[0], o0[1], o0[2], o0[3]);
    ((float4*)p0)[1] = make_float4(o0[4], o0[5], o0[6], o0[7]);
    float* p1 = p0 + plane;
    ((float4*)p1)[0] = make_float4(o1[0], o1[1], o1[2], o1[3]);
    ((float4*)p1)[1] = make_float4(o1[4], o1[5], o1[6], o1[7]);
}

// ---------------------------------------------------------------------------
extern "C" void kernel_launch(void* const* d_in, const int* in_sizes, int n_in,
                              void* d_out, int out_size) {
    const float* fmap1  = (const float*)d_in[0];
    const float* fmap2  = (const float*)d_in[1];
    const float* coords = (const float*)d_in[2];
    const float* flow   = (const float*)d_in[3];
    const float* mask   = (const float*)d_in[4];
    float* out = (float*)d_out;

    dim3 tb(32, 8);
    dim3 tg(HWv / 32, Cc / 32, Bb);
    transpose_f_k<<<tg, tb>>>(fmap1);
    transpose_h_k<<<tg, tb>>>(fmap2);
    pool_k<<<dim3(H1 * W1, Bb), 128>>>(1);
    pool_k<<<dim3(H2 * W2, Bb), 128>>>(2);
    pool_k<<<dim3(H3 * W3, Bb), 128>>>(3);
    lookup_k<<<dim3(Ww / 2, Hh / 2, Bb), 256>>>(coords);
    corr_t_k<<<dim3(HWv / 32, 11, Bb), tb>>>(out);
    upsample_k<<<Nn / 32, 256>>>(flow, mask, out);
}